// round 17
// baseline (speedup 1.0000x reference)
#include <cuda_runtime.h>
#include <cuda_fp16.h>
#include <cstdint>

#define BB   128
#define SSEQ 513
#define HH   256
#define SSH  (SSEQ * HH)
#define SBH  (BB * HH)

#define NX   (BB * SSEQ * HH)
#define NX8  (NX / 8)
#define NW   (5 * HH * HH)
#define NW8  (NW / 8)
#define NCVT (NX8 + NW8 + 32)

#define GRID  296                    // 2 CTAs x 148 SMs, all resident (regs cap occupancy at 2)
#define NTASK (2 * SSEQ)             // 1026 (n-half, s) tasks

#define KT    64
#define ROWB  144
#define TILEB (128 * ROWB)           // 18432
#define STAGE (2 * TILEB)            // X + W per slot = 36864
#define SMTOT (2 * STAGE + 16)       // + task broadcast word

__device__ __half gx[NX];            // [s][b][h] fp16
__device__ __half gw[NW];            // [widx][n][h] fp16
__device__ float  gbsum[HH];
__device__ unsigned int bar_ctr  = 0;   // monotonic epoch barrier (replay-safe)
__device__ unsigned int task_ctr = 0;   // reset each replay in phase 1

__device__ __forceinline__ uint32_t smem_u32(const void* p) {
    uint32_t a;
    asm("{ .reg .u64 t; cvta.to.shared.u64 t, %1; cvt.u32.u64 %0, t; }" : "=r"(a) : "l"(p));
    return a;
}
__device__ __forceinline__ void cpasync16(uint32_t dst, const void* src) {
    asm volatile("cp.async.ca.shared.global [%0], [%1], 16;" :: "r"(dst), "l"(src));
}
__device__ __forceinline__ void cp_commit() { asm volatile("cp.async.commit_group;"); }
__device__ __forceinline__ void cp_wait0()  { asm volatile("cp.async.wait_group 0;"); }
__device__ __forceinline__ void ldsm_x4(uint32_t* r, uint32_t addr) {
    asm volatile("ldmatrix.sync.aligned.m8n8.x4.shared.b16 {%0,%1,%2,%3}, [%4];"
                 : "=r"(r[0]), "=r"(r[1]), "=r"(r[2]), "=r"(r[3]) : "r"(addr));
}
__device__ __forceinline__ void mma_f16(float* d, const uint32_t* a, uint32_t b0, uint32_t b1) {
    asm volatile(
        "mma.sync.aligned.m16n8k16.row.col.f32.f16.f16.f32 "
        "{%0,%1,%2,%3}, {%4,%5,%6,%7}, {%8,%9}, {%0,%1,%2,%3};"
        : "+f"(d[0]), "+f"(d[1]), "+f"(d[2]), "+f"(d[3])
        : "r"(a[0]), "r"(a[1]), "r"(a[2]), "r"(a[3]), "r"(b0), "r"(b1));
}
__device__ __forceinline__ uint2 f4_to_h4(float4 v) {
    __half2 h0 = __floats2half2_rn(v.x, v.y);
    __half2 h1 = __floats2half2_rn(v.z, v.w);
    uint2 u;
    u.x = *reinterpret_cast<uint32_t*>(&h0);
    u.y = *reinterpret_cast<uint32_t*>(&h1);
    return u;
}

__global__ __launch_bounds__(256, 2)
void pmha_persist_kernel(const float* __restrict__ x,
                         const float* __restrict__ W,
                         const float* __restrict__ bias,
                         float* __restrict__ out)
{
    extern __shared__ char smem[];
    const uint32_t sb = smem_u32(smem);
    int* tsk = reinterpret_cast<int*>(smem + 2 * STAGE);
    const int tid  = threadIdx.x;
    const int lane = tid & 31;
    const int wid  = tid >> 5;

    // ================= phase 1: fp32 -> fp16 convert (x transposed) + bias presum =================
    for (uint32_t id = blockIdx.x * 256 + tid; id < NCVT; id += GRID * 256) {
        if (id < NX8) {
            const size_t f = (size_t)id * 8;
            const int b   = (int)(f / (SSEQ * HH));
            const int rem = (int)(f % (SSEQ * HH));
            const int s   = rem / HH;
            const int h   = rem % HH;
            float4 v0 = *reinterpret_cast<const float4*>(x + f);
            float4 v1 = *reinterpret_cast<const float4*>(x + f + 4);
            uint2 a = f4_to_h4(v0), c = f4_to_h4(v1);
            *reinterpret_cast<uint4*>(&gx[(size_t)s * SBH + (size_t)b * HH + h]) =
                make_uint4(a.x, a.y, c.x, c.y);
        } else if (id < NX8 + NW8) {
            const size_t f = (size_t)(id - NX8) * 8;
            float4 v0 = *reinterpret_cast<const float4*>(W + f);
            float4 v1 = *reinterpret_cast<const float4*>(W + f + 4);
            uint2 a = f4_to_h4(v0), c = f4_to_h4(v1);
            *reinterpret_cast<uint4*>(&gw[f]) = make_uint4(a.x, a.y, c.x, c.y);
        } else {
            const int t = (int)(id - NX8 - NW8);   // 0..31
            #pragma unroll
            for (int j = 0; j < 8; ++j) {
                const int c = t * 8 + j;
                float v = 0.0f;
                #pragma unroll
                for (int l = 0; l < 5; ++l) v += bias[l * HH + c];
                gbsum[c] = v;
            }
        }
    }
    if (blockIdx.x == 0 && tid == 0) atomicExch(&task_ctr, 0u);

    // ================= grid barrier (monotonic epoch; all 296 CTAs resident) =================
    __syncthreads();
    if (tid == 0) {
        __threadfence();
        unsigned old = atomicAdd(&bar_ctr, 1u);
        unsigned target = (old / GRID + 1u) * GRID;
        unsigned v;
        do {
            asm volatile("ld.acquire.gpu.u32 %0, [%1];" : "=r"(v) : "l"(&bar_ctr) : "memory");
        } while (v < target);
    }
    __syncthreads();

    // ================= phase 2: round-8 GEMM, dynamic (n-half, s) task queue =================
    const int tg  = lane >> 2;
    const int tig = lane & 3;
    const int wm  = (wid >> 2) * 64;
    const int wn  = (wid & 3) * 32;
    const int prow = tid >> 3;
    const int pc   = tid & 7;
    const int lr = lane & 15;
    const int lc = lane >> 4;

    uint32_t aA[4], aB[2];
    #pragma unroll
    for (int i = 0; i < 4; ++i)
        aA[i] = sb + (uint32_t)(wm + i * 16 + lr) * ROWB + lc * 16;
    #pragma unroll
    for (int jj = 0; jj < 2; ++jj)
        aB[jj] = sb + TILEB + (uint32_t)(wn + jj * 16 + lr) * ROWB + lc * 16;

    for (;;) {
        if (tid == 0) *tsk = (int)atomicAdd(&task_ctr, 1u);
        __syncthreads();                       // publishes *tsk; also retires prev task's smem readers
        const int t = *tsk;
        if (t >= NTASK) break;

        const int s    = t >> 1;
        const int n0   = (t & 1) * 128;
        const int widx = (s < 3) ? s : ((s & 1) ? 3 : 4);
        const __half* xs = gx + (size_t)s * SBH;
        const __half* Wp = gw + (size_t)widx * (HH * HH) + (size_t)n0 * HH;

        auto prefetch = [&](int kt) {
            const int k0 = kt * KT;
            const uint32_t base = sb + (kt & 1) * STAGE;
            #pragma unroll
            for (int q = 0; q < 4; ++q) {
                const int row = prow + q * 32;
                const uint32_t off = (uint32_t)row * ROWB + (uint32_t)pc * 16;
                cpasync16(base + off,         xs + (size_t)row * HH + k0 + pc * 8);
                cpasync16(base + TILEB + off, Wp + (size_t)row * HH + k0 + pc * 8);
            }
        };

        prefetch(0); cp_commit();

        float acc[4][4][4] = {};

        #pragma unroll
        for (int u = 0; u < 4; ++u) {
            cp_wait0();
            __syncthreads();
            if (u + 1 < 4) { prefetch(u + 1); cp_commit(); }

            const uint32_t stoff = (u & 1) * STAGE;
            #pragma unroll
            for (int ks = 0; ks < 4; ++ks) {
                const uint32_t off = stoff + ks * 32;
                uint32_t a[4][4], b[2][4];
                #pragma unroll
                for (int i = 0; i < 4; ++i) ldsm_x4(a[i], aA[i] + off);
                #pragma unroll
                for (int jj = 0; jj < 2; ++jj) ldsm_x4(b[jj], aB[jj] + off);
                #pragma unroll
                for (int i = 0; i < 4; ++i)
                    #pragma unroll
                    for (int j = 0; j < 4; ++j) {
                        const int jj = j >> 1, sel = j & 1;
                        mma_f16(acc[i][j], a[i], b[jj][sel], b[jj][sel + 2]);
                    }
            }
        }

        // epilogue: bias in regs, float2 stores
        float bA[4], bB[4];
        #pragma unroll
        for (int j = 0; j < 4; ++j) {
            const int c = wn + j * 8 + 2 * tig;
            bA[j] = gbsum[n0 + c];
            bB[j] = gbsum[n0 + c + 1];
        }
        #pragma unroll
        for (int i = 0; i < 4; ++i) {
            const int r0 = wm + i * 16 + tg;
            float* o0 = out + (size_t)r0 * SSH + (size_t)s * HH + n0;
            float* o1 = o0 + (size_t)8 * SSH;
            #pragma unroll
            for (int j = 0; j < 4; ++j) {
                const int c = wn + j * 8 + 2 * tig;
                float2 v0 = make_float2(acc[i][j][0] + bA[j], acc[i][j][1] + bB[j]);
                float2 v1 = make_float2(acc[i][j][2] + bA[j], acc[i][j][3] + bB[j]);
                *reinterpret_cast<float2*>(o0 + c) = v0;
                *reinterpret_cast<float2*>(o1 + c) = v1;
            }
        }
    }
}

extern "C" void kernel_launch(void* const* d_in, const int* in_sizes, int n_in,
                              void* d_out, int out_size)
{
    const float* x    = (const float*)d_in[0];   // [128, 513, 256]
    const float* W    = (const float*)d_in[1];   // [5, 256, 256]
    const float* bias = (const float*)d_in[2];   // [5, 256]
    float* out        = (float*)d_out;           // [128, 513, 4, 64]

    cudaFuncSetAttribute(pmha_persist_kernel, cudaFuncAttributeMaxDynamicSharedMemorySize, SMTOT);
    pmha_persist_kernel<<<GRID, 256, SMTOT>>>(x, W, bias, out);
}